// round 1
// baseline (speedup 1.0000x reference)
#include <cuda_runtime.h>
#include <cstdint>

#define BATCH 64
#define CIN   64
#define NNODE 4097
#define TNODE 4096
#define HID   128
#define LAT   64
#define NINST 128            // 2 encoders * 64 batch
#define LNE   (NNODE*HID)    // 524416 elems per LN instance
#define LNCH  32
#define CHSZ  (LNE/LNCH)     // 16388
#define MAXCH 8

// ---------------- scratch (device globals; no allocations allowed) ----------
__device__ float g_xt [(size_t)NINST * NNODE * CIN];   // 134 MB  (B,N,64) per inst
__device__ float g_y1 [(size_t)NINST * NNODE * HID];   // 268 MB
__device__ float g_y2 [(size_t)NINST * NNODE * HID];   // 268 MB
__device__ float g_Wr1[2 * 3 * CIN * HID];             // reordered (K,128)
__device__ float g_Wr2[2 * 3 * HID * HID];
__device__ float g_part[NINST * LNCH * 2];
__device__ float g_stats1[NINST * 2];
__device__ float g_stats2[NINST * 2];
__device__ float g_pmax[NINST * MAXCH * HID];

// ---------------- weight reorder: Wr[(k*C + c)*128 + o] = W[o,c,k] ----------
__global__ void prep_weights(const float* __restrict__ Wl1, const float* __restrict__ Wp1,
                             const float* __restrict__ Wl2, const float* __restrict__ Wp2) {
    int idx = blockIdx.x * blockDim.x + threadIdx.x;
    int stride = gridDim.x * blockDim.x;
    for (int i = idx; i < 2 * 3 * CIN * HID; i += stride) {
        int enc = i / (3 * CIN * HID);
        int rem = i % (3 * CIN * HID);
        int r = rem / HID, o = rem % HID;
        int k = r / CIN, c = r % CIN;
        const float* src = enc ? Wp1 : Wl1;
        g_Wr1[i] = src[(o * CIN + c) * 3 + k];
    }
    for (int i = idx; i < 2 * 3 * HID * HID; i += stride) {
        int enc = i / (3 * HID * HID);
        int rem = i % (3 * HID * HID);
        int r = rem / HID, o = rem % HID;
        int k = r / HID, c = r % HID;
        const float* src = enc ? Wp2 : Wl2;
        g_Wr2[i] = src[(o * HID + c) * 3 + k];
    }
}

// ---------------- transpose feats (B,C,N)->(inst,N,C) -----------------------
__global__ void transpose_kernel(const float* __restrict__ lf, const float* __restrict__ pf) {
    __shared__ float tile[32][33];
    int inst = blockIdx.z;
    int enc = inst >> 6, b = inst & 63;
    const float* src = (enc ? pf : lf) + (size_t)b * CIN * NNODE;
    int n0 = blockIdx.x * 32, c0 = blockIdx.y * 32;
    for (int i = threadIdx.y; i < 32; i += 8) {
        int c = c0 + i, n = n0 + threadIdx.x;
        if (c < CIN && n < NNODE) tile[i][threadIdx.x] = src[(size_t)c * NNODE + n];
    }
    __syncthreads();
    float* dst = g_xt + (size_t)inst * NNODE * CIN;
    for (int i = threadIdx.y; i < 32; i += 8) {
        int n = n0 + i, c = c0 + threadIdx.x;
        if (n < NNODE && c < CIN) dst[(size_t)n * CIN + c] = tile[threadIdx.x][i];
    }
}

// ---------------- tree-conv as tiled SGEMM ----------------------------------
// out[inst, n, o] = sum_{k,c} xin[inst, child(n,k), c] * Wr[enc][(k*C+c)*128+o] + bias[o]
template <int C>
__global__ void __launch_bounds__(256) conv_kernel(
        const float* __restrict__ xin, const float* __restrict__ Wr,
        const float* __restrict__ bias0, const float* __restrict__ bias1,
        const int* __restrict__ children, float* __restrict__ yout) {
    constexpr int K = 3 * C;
    __shared__ float sW[16][128];
    __shared__ float sG[16][68];
    __shared__ int   sCh[192];
    const int tid = threadIdx.x;
    const int enc = blockIdx.z, b = blockIdx.y, tileId = blockIdx.x;
    const int inst = enc * BATCH + b;
    const int n0 = 1 + tileId * 64;
    const float* xb = xin + (size_t)inst * NNODE * C;
    const float* Wb = Wr + (size_t)enc * K * 128;
    const float* bb = enc ? bias1 : bias0;

    if (tid < 192) sCh[tid] = children[(size_t)b * 3 * TNODE + 3 * (n0 - 1) + tid];
    // zero the null-node column once
    if (tileId == 0 && tid < 32)
        reinterpret_cast<float4*>(yout + (size_t)inst * NNODE * 128)[tid] = make_float4(0.f, 0.f, 0.f, 0.f);

    const int tm = tid >> 4, tn = tid & 15;
    float acc[8][4] = {};

    for (int kc = 0; kc < K; kc += 16) {
        const int k = kc / C;       // same for whole chunk (C % 16 == 0)
        const int cb = kc % C;
        __syncthreads();
        // W chunk: 2048 contiguous floats
        const float4* Ws = reinterpret_cast<const float4*>(Wb + (size_t)kc * 128);
        float4* sW4 = reinterpret_cast<float4*>(&sW[0][0]);
        sW4[tid] = Ws[tid];
        sW4[tid + 256] = Ws[tid + 256];
        // G chunk: gather 64 nodes x 16 channels
#pragma unroll
        for (int j = 0; j < 4; j++) {
            int i = tid + j * 256;
            int t = i >> 4, cc = i & 15;
            int chd = sCh[t * 3 + k];
            sG[cc][t] = xb[(size_t)chd * C + cb + cc];
        }
        __syncthreads();
#pragma unroll
        for (int kk = 0; kk < 16; kk++) {
            float4 w0 = *reinterpret_cast<const float4*>(&sW[kk][tm * 8]);
            float4 w1 = *reinterpret_cast<const float4*>(&sW[kk][tm * 8 + 4]);
            float4 gv = *reinterpret_cast<const float4*>(&sG[kk][tn * 4]);
            float wv[8] = {w0.x, w0.y, w0.z, w0.w, w1.x, w1.y, w1.z, w1.w};
            float gg[4] = {gv.x, gv.y, gv.z, gv.w};
#pragma unroll
            for (int i = 0; i < 8; i++)
#pragma unroll
                for (int j = 0; j < 4; j++) acc[i][j] += wv[i] * gg[j];
        }
    }

    float bv[8];
#pragma unroll
    for (int i = 0; i < 8; i++) bv[i] = bb[tm * 8 + i];
#pragma unroll
    for (int j = 0; j < 4; j++) {
        int n = n0 + tn * 4 + j;
        float* op = yout + ((size_t)inst * NNODE + n) * 128 + tm * 8;
        float4 o0 = make_float4(acc[0][j] + bv[0], acc[1][j] + bv[1], acc[2][j] + bv[2], acc[3][j] + bv[3]);
        float4 o1 = make_float4(acc[4][j] + bv[4], acc[5][j] + bv[5], acc[6][j] + bv[6], acc[7][j] + bv[7]);
        *reinterpret_cast<float4*>(op) = o0;
        *reinterpret_cast<float4*>(op + 4) = o1;
    }
}

// ---------------- layer-norm reductions (deterministic two-stage) -----------
__global__ void ln_reduce(const float* __restrict__ y, float* __restrict__ part) {
    const int inst = blockIdx.y, chunk = blockIdx.x, tid = threadIdx.x;
    const float* p = y + (size_t)inst * LNE + (size_t)chunk * CHSZ;
    float s = 0.f, q = 0.f;
    for (int i = tid; i < CHSZ; i += 256) { float v = p[i]; s += v; q += v * v; }
    __shared__ float ss[256], sq[256];
    ss[tid] = s; sq[tid] = q; __syncthreads();
    for (int o = 128; o > 0; o >>= 1) {
        if (tid < o) { ss[tid] += ss[tid + o]; sq[tid] += sq[tid + o]; }
        __syncthreads();
    }
    if (tid == 0) {
        part[(inst * LNCH + chunk) * 2 + 0] = ss[0];
        part[(inst * LNCH + chunk) * 2 + 1] = sq[0];
    }
}

__global__ void ln_finalize(const float* __restrict__ part, float* __restrict__ stats) {
    int inst = threadIdx.x;
    if (inst >= NINST) return;
    float s = 0.f, q = 0.f;
    for (int j = 0; j < LNCH; j++) {
        s += part[(inst * LNCH + j) * 2 + 0];
        q += part[(inst * LNCH + j) * 2 + 1];
    }
    const float n = (float)LNE;
    float mean = s / n;
    float var = (q - s * s / n) / (n - 1.0f);
    var = fmaxf(var, 0.f);
    float inv = 1.0f / (sqrtf(var) + 1e-5f);
    stats[inst * 2 + 0] = mean;
    stats[inst * 2 + 1] = inv;
}

__global__ void ln_apply_relu(float* __restrict__ y, const float* __restrict__ stats) {
    const size_t total4 = (size_t)NINST * LNE / 4;
    const int per_inst4 = LNE / 4;
    for (size_t idx = (size_t)blockIdx.x * blockDim.x + threadIdx.x; idx < total4;
         idx += (size_t)gridDim.x * blockDim.x) {
        int inst = (int)(idx / per_inst4);
        float mean = stats[inst * 2 + 0], inv = stats[inst * 2 + 1];
        float4 v = reinterpret_cast<float4*>(y)[idx];
        v.x = fmaxf((v.x - mean) * inv, 0.f);
        v.y = fmaxf((v.y - mean) * inv, 0.f);
        v.z = fmaxf((v.z - mean) * inv, 0.f);
        v.w = fmaxf((v.w - mean) * inv, 0.f);
        reinterpret_cast<float4*>(y)[idx] = v;
    }
}

// ---------------- column max over nodes (raw y2; LN+relu commutes with max) -
__global__ void max_kernel(const float* __restrict__ y, float* __restrict__ pmax) {
    const int inst = blockIdx.y, chunk = blockIdx.x, c = threadIdx.x;
    int r0 = chunk * 513;
    int r1 = min(r0 + 513, NNODE);
    float m = -3.4e38f;
    for (int r = r0; r < r1; r++)
        m = fmaxf(m, y[((size_t)inst * NNODE + r) * HID + c]);
    pmax[(inst * MAXCH + chunk) * HID + c] = m;
}

// ---------------- embed + FC head -------------------------------------------
__global__ void head_kernel(const float* __restrict__ pmax, const float* __restrict__ stats,
                            const float* __restrict__ Wmu, const float* __restrict__ bmu,
                            const float* __restrict__ Wlv, const float* __restrict__ blv,
                            float* __restrict__ out) {
    __shared__ float comb[2 * HID];
    const int b = blockIdx.x, t = threadIdx.x;  // 128 threads
    for (int enc = 0; enc < 2; enc++) {
        int inst = enc * BATCH + b;
        float m = -3.4e38f;
        for (int ch = 0; ch < MAXCH; ch++)
            m = fmaxf(m, pmax[(inst * MAXCH + ch) * HID + t]);
        float v = (m - stats[inst * 2 + 0]) * stats[inst * 2 + 1];
        comb[enc * HID + t] = fmaxf(v, 0.f);
    }
    __syncthreads();
    const float* Wt; const float* bt; float* op; int l;
    if (t < LAT) { Wt = Wmu; bt = bmu; op = out;                l = t; }
    else         { Wt = Wlv; bt = blv; op = out + BATCH * LAT;  l = t - LAT; }
    float s = bt[l];
#pragma unroll 8
    for (int j = 0; j < 2 * HID; j++) s += comb[j] * Wt[l * 2 * HID + j];
    op[b * LAT + l] = s;
}

// ---------------- driver -----------------------------------------------------
extern "C" void kernel_launch(void* const* d_in, const int* in_sizes, int n_in,
                              void* d_out, int out_size) {
    const float* lf  = (const float*)d_in[0];
    const float* pf  = (const float*)d_in[1];
    const int*   ch  = (const int*)d_in[2];
    const float* Wl1 = (const float*)d_in[3];
    const float* bl1 = (const float*)d_in[4];
    const float* Wl2 = (const float*)d_in[5];
    const float* bl2 = (const float*)d_in[6];
    const float* Wp1 = (const float*)d_in[7];
    const float* bp1 = (const float*)d_in[8];
    const float* Wp2 = (const float*)d_in[9];
    const float* bp2 = (const float*)d_in[10];
    const float* Wmu = (const float*)d_in[11];
    const float* bmu = (const float*)d_in[12];
    const float* Wlv = (const float*)d_in[13];
    const float* blv = (const float*)d_in[14];
    float* out = (float*)d_out;

    float *xt, *y1, *y2, *Wr1, *Wr2, *part, *st1, *st2, *pmax;
    cudaGetSymbolAddress((void**)&xt,   g_xt);
    cudaGetSymbolAddress((void**)&y1,   g_y1);
    cudaGetSymbolAddress((void**)&y2,   g_y2);
    cudaGetSymbolAddress((void**)&Wr1,  g_Wr1);
    cudaGetSymbolAddress((void**)&Wr2,  g_Wr2);
    cudaGetSymbolAddress((void**)&part, g_part);
    cudaGetSymbolAddress((void**)&st1,  g_stats1);
    cudaGetSymbolAddress((void**)&st2,  g_stats2);
    cudaGetSymbolAddress((void**)&pmax, g_pmax);

    prep_weights<<<192, 512>>>(Wl1, Wp1, Wl2, Wp2);
    transpose_kernel<<<dim3((NNODE + 31) / 32, 2, NINST), dim3(32, 8)>>>(lf, pf);

    conv_kernel<CIN><<<dim3(TNODE / 64, BATCH, 2), 256>>>(xt, Wr1, bl1, bp1, ch, y1);
    ln_reduce<<<dim3(LNCH, NINST), 256>>>(y1, part);
    ln_finalize<<<1, 128>>>(part, st1);
    ln_apply_relu<<<4096, 256>>>(y1, st1);

    conv_kernel<HID><<<dim3(TNODE / 64, BATCH, 2), 256>>>(y1, Wr2, bl2, bp2, ch, y2);
    ln_reduce<<<dim3(LNCH, NINST), 256>>>(y2, part);
    ln_finalize<<<1, 128>>>(part, st2);
    max_kernel<<<dim3(MAXCH, NINST), HID>>>(y2, pmax);

    head_kernel<<<BATCH, 128>>>(pmax, st2, Wmu, bmu, Wlv, blv, out);
}

// round 3
// speedup vs baseline: 2.9767x; 2.9767x over previous
#include <cuda_runtime.h>
#include <cstdint>

#define BATCH 64
#define CIN   64
#define NNODE 4097
#define TNODE 4096
#define HID   128
#define LAT   64
#define NINST 128
#define NTILE 32                 // 4096 nodes / 128-node tiles
#define LNE   (NNODE*HID)

// ---------------- scratch ----------------------------------------------------
__device__ float g_xt [(size_t)NINST * NNODE * CIN];
__device__ float g_y1 [(size_t)NINST * NNODE * HID];
__device__ float g_Wa1[2 * HID * 3 * CIN];    // [enc][o][k], k = k3*C + c
__device__ float g_Wa2[2 * HID * 3 * HID];
__device__ float g_part1[NINST * NTILE * 2];
__device__ float g_part2[NINST * NTILE * 2];
__device__ float g_st1[NINST * 2];
__device__ float g_st2[NINST * 2];
__device__ float g_pmax[NINST * NTILE * HID];

__device__ __forceinline__ uint32_t f2tf32(float v) {
    uint32_t r;
    asm("cvt.rna.tf32.f32 %0, %1;" : "=r"(r) : "f"(v));
    return r;
}
__device__ __forceinline__ void mma_tf32(float* d, const uint32_t* a, uint32_t b0, uint32_t b1) {
    asm volatile(
        "mma.sync.aligned.m16n8k8.row.col.f32.tf32.tf32.f32 "
        "{%0,%1,%2,%3}, {%4,%5,%6,%7}, {%8,%9}, {%0,%1,%2,%3};"
        : "+f"(d[0]), "+f"(d[1]), "+f"(d[2]), "+f"(d[3])
        : "r"(a[0]), "r"(a[1]), "r"(a[2]), "r"(a[3]), "r"(b0), "r"(b1));
}

// ---------------- weight reorder: Wa[enc][o][k3*C+c] = W[o][c][k3] -----------
__global__ void prep_weights(const float* __restrict__ Wl1, const float* __restrict__ Wp1,
                             const float* __restrict__ Wl2, const float* __restrict__ Wp2) {
    int idx = blockIdx.x * blockDim.x + threadIdx.x;
    int stride = gridDim.x * blockDim.x;
    for (int i = idx; i < 2 * HID * 3 * CIN; i += stride) {
        int enc = i / (HID * 3 * CIN);
        int rem = i % (HID * 3 * CIN);
        int o = rem / (3 * CIN), k = rem % (3 * CIN);
        int k3 = k / CIN, c = k % CIN;
        g_Wa1[i] = (enc ? Wp1 : Wl1)[(o * CIN + c) * 3 + k3];
    }
    for (int i = idx; i < 2 * HID * 3 * HID; i += stride) {
        int enc = i / (HID * 3 * HID);
        int rem = i % (HID * 3 * HID);
        int o = rem / (3 * HID), k = rem % (3 * HID);
        int k3 = k / HID, c = k % HID;
        g_Wa2[i] = (enc ? Wp2 : Wl2)[(o * HID + c) * 3 + k3];
    }
}

// ---------------- transpose feats (B,C,N)->(inst,N,C) -----------------------
__global__ void transpose_kernel(const float* __restrict__ lf, const float* __restrict__ pf) {
    __shared__ float tile[32][33];
    int inst = blockIdx.z;
    int enc = inst >> 6, b = inst & 63;
    const float* src = (enc ? pf : lf) + (size_t)b * CIN * NNODE;
    int n0 = blockIdx.x * 32, c0 = blockIdx.y * 32;
    for (int i = threadIdx.y; i < 32; i += 8) {
        int c = c0 + i, n = n0 + threadIdx.x;
        if (c < CIN && n < NNODE) tile[i][threadIdx.x] = src[(size_t)c * NNODE + n];
    }
    __syncthreads();
    float* dst = g_xt + (size_t)inst * NNODE * CIN;
    for (int i = threadIdx.y; i < 32; i += 8) {
        int n = n0 + i, c = c0 + threadIdx.x;
        if (n < NNODE && c < CIN) dst[(size_t)n * CIN + c] = tile[threadIdx.x][i];
    }
}

// ---------------- tensor-core tree conv (mma.sync tf32) ----------------------
// D[m][n] = sum_k W[m][k] * G[n][k];  A=W row-major, B=G "col-major" (n,k)
template <int C>
__global__ void __launch_bounds__(256, 2) conv_tc(
        const float* __restrict__ xin, const float* __restrict__ Wa,
        const float* __restrict__ bias0, const float* __restrict__ bias1,
        const int* __restrict__ children,
        const float* __restrict__ stats,     // LN stats of the INPUT (conv2) or null
        float* __restrict__ yout,            // conv1: raw output; conv2: null
        float* __restrict__ part,            // per-tile (sum, sumsq) of output
        float* __restrict__ pmax) {          // conv2: per-tile per-channel max
    constexpr int K = 3 * C;
    constexpr int NCH = K / 32;

    __shared__ float sA[128][36];            // W chunk  [m][k]
    __shared__ float sB[128][36];            // G chunk  [n][k]
    __shared__ int   sCh[384];
    __shared__ float sRs[256], sRq[256];
    __shared__ float sMax[4][128];

    const int tid = threadIdx.x;
    const int w = tid >> 5, lane = tid & 31;
    const int g = lane >> 2, t = lane & 3;
    const int wm = w >> 2, wn = w & 3;       // warp tile: 64(M) x 32(N)
    const int mbase = wm * 64, nbase = wn * 32;

    const int enc = blockIdx.z, b = blockIdx.y, tile = blockIdx.x;
    const int inst = enc * BATCH + b;
    const int n0 = 1 + tile * 128;

    const int* csrc = children + (size_t)b * 3 * TNODE + 3 * (n0 - 1);
    sCh[tid] = csrc[tid];
    if (tid < 128) sCh[256 + tid] = csrc[256 + tid];

    float mean = 0.f, inv = 0.f;
    const bool doLN = (stats != nullptr);
    if (doLN) { mean = stats[inst * 2 + 0]; inv = stats[inst * 2 + 1]; }

    const float* xb = xin + (size_t)inst * NNODE * C;
    const float* Wb = Wa + (size_t)enc * HID * K;
    const float* bb = enc ? bias1 : bias0;

    float acc[4][4][4];
#pragma unroll
    for (int mi = 0; mi < 4; mi++)
#pragma unroll
        for (int ni = 0; ni < 4; ni++)
#pragma unroll
            for (int r = 0; r < 4; r++) acc[mi][ni][r] = 0.f;

    const int row = tid >> 1, half = tid & 1;   // fill role: 128 rows x 2 halves

    for (int ck = 0; ck < NCH; ck++) {
        const int kc = ck * 32;
        const int kch = kc / C, cb = kc % C;
        __syncthreads();
        // A: W rows (m = row), 16 tf32 per thread
        {
            const float4* ws = reinterpret_cast<const float4*>(Wb + (size_t)row * K + kc + half * 16);
            uint32_t* dst = reinterpret_cast<uint32_t*>(&sA[row][half * 16]);
#pragma unroll
            for (int j = 0; j < 4; j++) {
                float4 v = ws[j];
                uint4 u = make_uint4(f2tf32(v.x), f2tf32(v.y), f2tf32(v.z), f2tf32(v.w));
                *reinterpret_cast<uint4*>(dst + j * 4) = u;
            }
        }
        // B: gathered child features (n = row), fused LN+relu for conv2
        {
            const int chd = sCh[row * 3 + kch];
            const float4* gs = reinterpret_cast<const float4*>(xb + (size_t)chd * C + cb + half * 16);
            uint32_t* dst = reinterpret_cast<uint32_t*>(&sB[row][half * 16]);
#pragma unroll
            for (int j = 0; j < 4; j++) {
                float4 v = gs[j];
                if (doLN) {
                    v.x = fmaxf((v.x - mean) * inv, 0.f);
                    v.y = fmaxf((v.y - mean) * inv, 0.f);
                    v.z = fmaxf((v.z - mean) * inv, 0.f);
                    v.w = fmaxf((v.w - mean) * inv, 0.f);
                }
                uint4 u = make_uint4(f2tf32(v.x), f2tf32(v.y), f2tf32(v.z), f2tf32(v.w));
                *reinterpret_cast<uint4*>(dst + j * 4) = u;
            }
        }
        __syncthreads();
#pragma unroll
        for (int ks = 0; ks < 4; ks++) {
            const int k0 = ks * 8;
            uint32_t af[4][4];
#pragma unroll
            for (int mi = 0; mi < 4; mi++) {
                af[mi][0] = __float_as_uint(sA[mbase + mi * 16 + g][k0 + t]);
                af[mi][1] = __float_as_uint(sA[mbase + mi * 16 + g + 8][k0 + t]);
                af[mi][2] = __float_as_uint(sA[mbase + mi * 16 + g][k0 + t + 4]);
                af[mi][3] = __float_as_uint(sA[mbase + mi * 16 + g + 8][k0 + t + 4]);
            }
#pragma unroll
            for (int ni = 0; ni < 4; ni++) {
                uint32_t b0 = __float_as_uint(sB[nbase + ni * 8 + g][k0 + t]);
                uint32_t b1 = __float_as_uint(sB[nbase + ni * 8 + g][k0 + t + 4]);
#pragma unroll
                for (int mi = 0; mi < 4; mi++) mma_tf32(acc[mi][ni], af[mi], b0, b1);
            }
        }
    }

    // ---------------- epilogue ------------------------------------------------
    float bv[4][2];
#pragma unroll
    for (int mi = 0; mi < 4; mi++) {
        bv[mi][0] = bb[mbase + mi * 16 + g];
        bv[mi][1] = bb[mbase + mi * 16 + g + 8];
    }
    float lsum = 0.f, lsq = 0.f;

    if (yout) {
        float* yb = yout + ((size_t)inst * NNODE + n0) * HID;
#pragma unroll
        for (int mi = 0; mi < 4; mi++)
#pragma unroll
            for (int ni = 0; ni < 4; ni++)
#pragma unroll
                for (int r = 0; r < 4; r++) {
                    float v = acc[mi][ni][r] + bv[mi][r >> 1];
                    int m = mbase + mi * 16 + g + ((r >> 1) ? 8 : 0);
                    int n = nbase + ni * 8 + t * 2 + (r & 1);
                    yb[(size_t)n * HID + m] = v;
                    lsum += v; lsq += v * v;
                }
        if (tile == 0 && tid < 32)
            reinterpret_cast<float4*>(yout + (size_t)inst * NNODE * HID)[tid] =
                make_float4(0.f, 0.f, 0.f, 0.f);
    } else {
        float mx[4][2];
#pragma unroll
        for (int mi = 0; mi < 4; mi++) { mx[mi][0] = -3.4e38f; mx[mi][1] = -3.4e38f; }
#pragma unroll
        for (int mi = 0; mi < 4; mi++)
#pragma unroll
            for (int ni = 0; ni < 4; ni++)
#pragma unroll
                for (int r = 0; r < 4; r++) {
                    float v = acc[mi][ni][r] + bv[mi][r >> 1];
                    mx[mi][r >> 1] = fmaxf(mx[mi][r >> 1], v);
                    lsum += v; lsq += v * v;
                }
        // reduce max over the 4 lanes sharing a row (xor on lane%4 bits)
#pragma unroll
        for (int mi = 0; mi < 4; mi++)
#pragma unroll
            for (int h = 0; h < 2; h++) {
                float m0 = mx[mi][h];
                m0 = fmaxf(m0, __shfl_xor_sync(0xFFFFFFFF, m0, 1));
                m0 = fmaxf(m0, __shfl_xor_sync(0xFFFFFFFF, m0, 2));
                mx[mi][h] = m0;
            }
        if (t == 0) {
#pragma unroll
            for (int mi = 0; mi < 4; mi++) {
                sMax[wn][mbase + mi * 16 + g] = mx[mi][0];
                sMax[wn][mbase + mi * 16 + g + 8] = mx[mi][1];
            }
        }
    }

    sRs[tid] = lsum; sRq[tid] = lsq;
    __syncthreads();
    for (int o = 128; o > 0; o >>= 1) {
        if (tid < o) { sRs[tid] += sRs[tid + o]; sRq[tid] += sRq[tid + o]; }
        __syncthreads();
    }
    if (tid == 0) {
        part[(inst * NTILE + tile) * 2 + 0] = sRs[0];
        part[(inst * NTILE + tile) * 2 + 1] = sRq[0];
    }
    if (!yout && tid < 128) {
        float m0 = fmaxf(fmaxf(sMax[0][tid], sMax[1][tid]),
                         fmaxf(sMax[2][tid], sMax[3][tid]));
        pmax[(inst * NTILE + tile) * HID + tid] = m0;
    }
}

// ---------------- LN stat finalize -------------------------------------------
__global__ void ln_finalize(const float* __restrict__ part, float* __restrict__ stats) {
    int inst = threadIdx.x;
    if (inst >= NINST) return;
    float s = 0.f, q = 0.f;
    for (int j = 0; j < NTILE; j++) {
        s += part[(inst * NTILE + j) * 2 + 0];
        q += part[(inst * NTILE + j) * 2 + 1];
    }
    const float n = (float)LNE;
    float m = s / n;
    float var = (q - s * s / n) / (n - 1.0f);
    var = fmaxf(var, 0.f);
    stats[inst * 2 + 0] = m;
    stats[inst * 2 + 1] = 1.0f / (sqrtf(var) + 1e-5f);
}

// ---------------- head: tile-max reduce, LN2+relu, FC ------------------------
__global__ void head_kernel(const float* __restrict__ pmax, const float* __restrict__ stats,
                            const float* __restrict__ Wmu, const float* __restrict__ bmu,
                            const float* __restrict__ Wlv, const float* __restrict__ blv,
                            float* __restrict__ out) {
    __shared__ float comb[2 * HID];
    const int b = blockIdx.x, t = threadIdx.x;   // 128 threads
    for (int enc = 0; enc < 2; enc++) {
        int inst = enc * BATCH + b;
        float mx = 0.f;                           // null column raw value
        for (int tl = 0; tl < NTILE; tl++)
            mx = fmaxf(mx, pmax[(inst * NTILE + tl) * HID + t]);
        float v = (mx - stats[inst * 2 + 0]) * stats[inst * 2 + 1];
        comb[enc * HID + t] = fmaxf(v, 0.f);
    }
    __syncthreads();
    const float* Wt; const float* bt; float* op; int l;
    if (t < LAT) { Wt = Wmu; bt = bmu; op = out;               l = t; }
    else         { Wt = Wlv; bt = blv; op = out + BATCH * LAT; l = t - LAT; }
    float s = bt[l];
#pragma unroll 8
    for (int j = 0; j < 2 * HID; j++) s += comb[j] * Wt[l * 2 * HID + j];
    op[b * LAT + l] = s;
}

// ---------------- driver -----------------------------------------------------
extern "C" void kernel_launch(void* const* d_in, const int* in_sizes, int n_in,
                              void* d_out, int out_size) {
    const float* lf  = (const float*)d_in[0];
    const float* pf  = (const float*)d_in[1];
    const int*   ch  = (const int*)d_in[2];
    const float* Wl1 = (const float*)d_in[3];
    const float* bl1 = (const float*)d_in[4];
    const float* Wl2 = (const float*)d_in[5];
    const float* bl2 = (const float*)d_in[6];
    const float* Wp1 = (const float*)d_in[7];
    const float* bp1 = (const float*)d_in[8];
    const float* Wp2 = (const float*)d_in[9];
    const float* bp2 = (const float*)d_in[10];
    const float* Wmu = (const float*)d_in[11];
    const float* bmu = (const float*)d_in[12];
    const float* Wlv = (const float*)d_in[13];
    const float* blv = (const float*)d_in[14];
    float* out = (float*)d_out;

    float *xt, *y1, *Wa1, *Wa2, *p1, *p2, *st1, *st2, *pmax;
    cudaGetSymbolAddress((void**)&xt,   g_xt);
    cudaGetSymbolAddress((void**)&y1,   g_y1);
    cudaGetSymbolAddress((void**)&Wa1,  g_Wa1);
    cudaGetSymbolAddress((void**)&Wa2,  g_Wa2);
    cudaGetSymbolAddress((void**)&p1,   g_part1);
    cudaGetSymbolAddress((void**)&p2,   g_part2);
    cudaGetSymbolAddress((void**)&st1,  g_st1);
    cudaGetSymbolAddress((void**)&st2,  g_st2);
    cudaGetSymbolAddress((void**)&pmax, g_pmax);

    prep_weights<<<96, 512>>>(Wl1, Wp1, Wl2, Wp2);
    transpose_kernel<<<dim3((NNODE + 31) / 32, 2, NINST), dim3(32, 8)>>>(lf, pf);

    conv_tc<CIN><<<dim3(NTILE, BATCH, 2), 256>>>(xt, Wa1, bl1, bp1, ch,
                                                 nullptr, y1, p1, nullptr);
    ln_finalize<<<1, 128>>>(p1, st1);
    conv_tc<HID><<<dim3(NTILE, BATCH, 2), 256>>>(y1, Wa2, bl2, bp2, ch,
                                                 st1, nullptr, p2, pmax);
    ln_finalize<<<1, 128>>>(p2, st2);
    head_kernel<<<BATCH, 128>>>(pmax, st2, Wmu, bmu, Wlv, blv, out);
}